// round 3
// baseline (speedup 1.0000x reference)
#include <cuda_runtime.h>

#define N_NODES 100000
#define E_EDGES 1600000
#define E_TOT   (E_EDGES + N_NODES)
#define DIM     128
#define HC      50          // H*C
#define HCP     52          // padded row (13 float4)
#define NHEADS  5
#define NGRAPH  256
#define NEG_SLOPE 0.2f

// ---------------- scratch (static device globals; 16B-aligned for v4 ops) ---
__device__ __align__(16) float g_xw   [N_NODES * HCP];
__device__ __align__(16) float g_asrc [N_NODES * 8];
__device__ __align__(16) float g_adst [N_NODES * 8];
__device__ __align__(16) float g_num  [N_NODES * HCP];
__device__ __align__(16) float g_den  [N_NODES * 8];
__device__ __align__(16) float g_gsum [NGRAPH * HCP];
__device__ __align__(16) float g_cnt  [NGRAPH];

// ---------------- vectorized global reductions (sm_90+) ---------------------
__device__ __forceinline__ void red4(float* p, float a, float b, float c, float d) {
    asm volatile("red.global.add.v4.f32 [%0], {%1,%2,%3,%4};"
                 :: "l"(p), "f"(a), "f"(b), "f"(c), "f"(d) : "memory");
}
__device__ __forceinline__ void red1(float* p, float a) {
    asm volatile("red.global.add.f32 [%0], %1;" :: "l"(p), "f"(a) : "memory");
}

// ---------------- K0: zero accumulators -------------------------------------
__global__ void k_init() {
    int i = blockIdx.x * blockDim.x + threadIdx.x;
    int stride = gridDim.x * blockDim.x;
    for (int j = i; j < N_NODES * HCP; j += stride) g_num[j] = 0.f;
    for (int j = i; j < N_NODES * 8;   j += stride) g_den[j] = 0.f;
    for (int j = i; j < NGRAPH * HCP;  j += stride) g_gsum[j] = 0.f;
    for (int j = i; j < NGRAPH;        j += stride) g_cnt[j]  = 0.f;
}

// ---------------- K1: xw = x@W, plus per-head attention scalars --------------
__global__ __launch_bounds__(32) void k_gemm(const float* __restrict__ x,
                                             const float* __restrict__ W,
                                             const float* __restrict__ att_src,
                                             const float* __restrict__ att_dst) {
    __shared__ float xs[32 * 129];
    __shared__ float ws[DIM * HCP];
    __shared__ float s_as[HC], s_ad[HC];

    int t  = threadIdx.x;
    int n0 = blockIdx.x * 32;

    for (int i = t; i < DIM * HCP; i += 32) {
        int r = i / HCP, c = i - r * HCP;
        ws[i] = (c < HC) ? W[r * HC + c] : 0.f;
    }
    for (int i = t; i < HC; i += 32) { s_as[i] = att_src[i]; s_ad[i] = att_dst[i]; }

    int rows = N_NODES - n0; if (rows > 32) rows = 32;
    const float4* xg = (const float4*)(x + (long long)n0 * DIM);
    for (int i = t; i < rows * 32; i += 32) {
        int r = i >> 5, c4 = i & 31;
        float4 v = xg[r * 32 + c4];
        float* p = &xs[r * 129 + c4 * 4];
        p[0] = v.x; p[1] = v.y; p[2] = v.z; p[3] = v.w;
    }
    __syncthreads();

    int n = n0 + t;
    if (n >= N_NODES) return;

    float4 acc[13];
#pragma unroll
    for (int j = 0; j < 13; j++) acc[j] = make_float4(0.f, 0.f, 0.f, 0.f);

#pragma unroll 4
    for (int k = 0; k < DIM; k++) {
        float xv = xs[t * 129 + k];
        const float4* wr = (const float4*)&ws[k * HCP];
#pragma unroll
        for (int j = 0; j < 13; j++) {
            float4 w4 = wr[j];
            acc[j].x += xv * w4.x; acc[j].y += xv * w4.y;
            acc[j].z += xv * w4.z; acc[j].w += xv * w4.w;
        }
    }

    float4* op = (float4*)(g_xw + n * HCP);
#pragma unroll
    for (int j = 0; j < 13; j++) op[j] = acc[j];

    const float* fa = (const float*)acc;
#pragma unroll
    for (int h = 0; h < NHEADS; h++) {
        float sa = 0.f, sd = 0.f;
#pragma unroll
        for (int c = 0; c < 10; c++) {
            float v = fa[h * 10 + c];
            sa += v * s_as[h * 10 + c];
            sd += v * s_ad[h * 10 + c];
        }
        g_asrc[n * 8 + h] = sa;
        g_adst[n * 8 + h] = sd;
    }
}

// ---------------- K2: single edge pass (softmax weights + weighted scatter) --
#define HIDX(c) ((c) < 50 ? (c) / 10 : 4)

__global__ void k_edge(const int* __restrict__ ei) {
    int e = blockIdx.x * blockDim.x + threadIdx.x;
    if (e >= E_TOT) return;

    int s, d;
    if (e < E_EDGES) {
        s = __ldg(ei + e);
        d = __ldg(ei + E_EDGES + e);
    } else {
        s = d = e - E_EDGES;                 // self loop
    }

    float4 a0 = __ldg((const float4*)(g_asrc + s * 8));
    float  a4 = __ldg(g_asrc + s * 8 + 4);
    float4 b0 = __ldg((const float4*)(g_adst + d * 8));
    float  b4 = __ldg(g_adst + d * 8 + 4);

    float w[NHEADS];
    {
        float l;
        l = a0.x + b0.x; l = l > 0.f ? l : NEG_SLOPE * l; w[0] = __expf(l);
        l = a0.y + b0.y; l = l > 0.f ? l : NEG_SLOPE * l; w[1] = __expf(l);
        l = a0.z + b0.z; l = l > 0.f ? l : NEG_SLOPE * l; w[2] = __expf(l);
        l = a0.w + b0.w; l = l > 0.f ? l : NEG_SLOPE * l; w[3] = __expf(l);
        l = a4   + b4;   l = l > 0.f ? l : NEG_SLOPE * l; w[4] = __expf(l);
    }

    red4(g_den + d * 8, w[0], w[1], w[2], w[3]);
    red1(g_den + d * 8 + 4, w[4]);

    const float4* xp = (const float4*)(g_xw + s * HCP);
    float* np = g_num + d * HCP;
#pragma unroll
    for (int j = 0; j < 13; j++) {
        float4 v = __ldg(xp + j);
        const int c0 = 4 * j;
        red4(np + c0,
             v.x * w[HIDX(c0 + 0)],
             v.y * w[HIDX(c0 + 1)],
             v.z * w[HIDX(c0 + 2)],
             v.w * w[HIDX(c0 + 3)]);
    }
}

// ---------------- K3: normalize, bias, ELU, graph mean-pool accumulate -------
__device__ __forceinline__ float eluf(float v) {
    return v > 0.f ? v : (expm1f(v));
}

__global__ void k_node(const float* __restrict__ bias,
                       const int* __restrict__ batch) {
    __shared__ float sb[HC];
    if (threadIdx.x < HC) sb[threadIdx.x] = bias[threadIdx.x];
    __syncthreads();

    int n = blockIdx.x * blockDim.x + threadIdx.x;
    if (n >= N_NODES) return;

    float4 d0 = __ldg((const float4*)(g_den + n * 8));
    float  d4 = __ldg(g_den + n * 8 + 4);
    float inv_den[NHEADS] = { 1.f / d0.x, 1.f / d0.y, 1.f / d0.z, 1.f / d0.w, 1.f / d4 };

    int g = __ldg(batch + n);
    const float4* npv = (const float4*)(g_num + n * HCP);

#pragma unroll
    for (int j = 0; j < 13; j++) {
        float4 v = __ldg(npv + j);
        const int c0 = 4 * j;
        float4 o;
        o.x = (c0 + 0 < 50) ? eluf(v.x * inv_den[HIDX(c0 + 0)] + sb[c0 + 0]) : 0.f;
        o.y = (c0 + 1 < 50) ? eluf(v.y * inv_den[HIDX(c0 + 1)] + sb[c0 + 1]) : 0.f;
        o.z = (c0 + 2 < 50) ? eluf(v.z * inv_den[HIDX(c0 + 2)] + sb[c0 + 2]) : 0.f;
        o.w = (c0 + 3 < 50) ? eluf(v.w * inv_den[HIDX(c0 + 3)] + sb[c0 + 3]) : 0.f;
        red4(g_gsum + g * HCP + c0, o.x, o.y, o.z, o.w);
    }
    red1(g_cnt + g, 1.f);
}

// ---------------- K4: h = gsum/cnt ; y = sigmoid(h @ lin_w + lin_b) ----------
__global__ void k_final(const float* __restrict__ lin_w,
                        const float* __restrict__ lin_b,
                        float* __restrict__ out, int out_size) {
    int g = threadIdx.x;                      // 256 threads, one per graph
    float cnt = g_cnt[g];
    float inv = 1.f / fmaxf(cnt, 1.f);
    float dot = 0.f;
#pragma unroll
    for (int c = 0; c < HC; c++) {
        float h = g_gsum[g * HCP + c] * inv;
        int idx = g * HC + c;
        if (idx < out_size) out[idx] = h;
        dot += h * __ldg(lin_w + c);
    }
    float y = 1.f / (1.f + __expf(-(dot + __ldg(lin_b))));
    int yidx = NGRAPH * HC + g;
    if (yidx < out_size) out[yidx] = y;
}

// ---------------- launch -----------------------------------------------------
extern "C" void kernel_launch(void* const* d_in, const int* in_sizes, int n_in,
                              void* d_out, int out_size) {
    const float* x       = (const float*)d_in[0];
    const float* W       = (const float*)d_in[1];
    const float* att_src = (const float*)d_in[2];
    const float* att_dst = (const float*)d_in[3];
    const float* bias    = (const float*)d_in[4];
    const float* lin_w   = (const float*)d_in[5];
    const float* lin_b   = (const float*)d_in[6];
    const int*   ei      = (const int*)d_in[7];    // int32 (JAX x64 disabled)
    const int*   batch   = (const int*)d_in[8];    // int32
    float*       out     = (float*)d_out;

    k_init <<<512, 256>>>();
    k_gemm <<<(N_NODES + 31) / 32, 32>>>(x, W, att_src, att_dst);
    k_edge <<<(E_TOT + 255) / 256, 256>>>(ei);
    k_node <<<(N_NODES + 255) / 256, 256>>>(bias, batch);
    k_final<<<1, 256>>>(lin_w, lin_b, out, out_size);
}

// round 4
// speedup vs baseline: 1.6016x; 1.6016x over previous
#include <cuda_runtime.h>

#define N_NODES 100000
#define E_EDGES 1600000
#define E_TOT   (E_EDGES + N_NODES)
#define DIM     128
#define HC      50          // H*C
#define HCP     52          // padded row (13 float4)
#define NHEADS  5
#define NGRAPH  256
#define NEG_SLOPE 0.2f
#define NCHUNK  1024        // scan chunk
#define NBLK_SCAN ((N_NODES + NCHUNK - 1) / NCHUNK)   // 98

// ---------------- scratch (static device globals) ---------------------------
__device__ __align__(16) float g_xw   [N_NODES * HCP];   // projected features (pads zero)
__device__ __align__(16) float g_asrc [N_NODES * 8];
__device__ __align__(16) float g_adst [N_NODES * 8];
__device__ __align__(16) float g_gsum [NGRAPH * HCP];
__device__ __align__(16) float g_cnt  [NGRAPH];
__device__ int   g_deg  [N_NODES];     // degree incl. self-loop
__device__ int   g_offl [N_NODES];     // chunk-local exclusive prefix
__device__ int   g_bpre [128];         // per-chunk base
__device__ int   g_bsum [128];
__device__ int   g_fill [N_NODES];
__device__ int   g_csrc [E_TOT];       // CSR: src ids grouped by dst

// ---------------- reductions -------------------------------------------------
__device__ __forceinline__ void red4(float* p, float a, float b, float c, float d) {
    asm volatile("red.global.add.v4.f32 [%0], {%1,%2,%3,%4};"
                 :: "l"(p), "f"(a), "f"(b), "f"(c), "f"(d) : "memory");
}
__device__ __forceinline__ void red1(float* p, float a) {
    asm volatile("red.global.add.f32 [%0], %1;" :: "l"(p), "f"(a) : "memory");
}

// ---------------- K0: init ---------------------------------------------------
__global__ void k_init() {
    int i = blockIdx.x * blockDim.x + threadIdx.x;
    int stride = gridDim.x * blockDim.x;
    for (int j = i; j < N_NODES; j += stride) { g_deg[j] = 1; g_fill[j] = 0; }
    for (int j = i; j < NGRAPH * HCP; j += stride) g_gsum[j] = 0.f;
    for (int j = i; j < NGRAPH; j += stride) g_cnt[j] = 0.f;
}

// ---------------- K1: xw = x@W  (128 thr = 4 col-groups x 32 nodes) ----------
__global__ __launch_bounds__(128) void k_gemm(const float* __restrict__ x,
                                              const float* __restrict__ W) {
    __shared__ float xs[32 * 129];
    __shared__ float ws[64 * HCP];

    int t  = threadIdx.x;
    int cg = t >> 5, ln = t & 31;
    int n0 = blockIdx.x * 32;

    const float4* xg = (const float4*)(x + (size_t)n0 * DIM);
    for (int i = t; i < 32 * 32; i += 128) {
        int r = i >> 5, c4 = i & 31;
        float4 v = xg[r * 32 + c4];
        float* p = &xs[r * 129 + c4 * 4];
        p[0] = v.x; p[1] = v.y; p[2] = v.z; p[3] = v.w;
    }

    float4 acc[4];
#pragma unroll
    for (int j = 0; j < 4; j++) acc[j] = make_float4(0.f, 0.f, 0.f, 0.f);

    for (int half = 0; half < 2; half++) {
        __syncthreads();
        for (int i = t; i < 64 * HCP; i += 128) {
            int r = i / HCP, c = i - r * HCP;
            ws[i] = (c < HC) ? W[(half * 64 + r) * HC + c] : 0.f;
        }
        __syncthreads();
#pragma unroll 4
        for (int k = 0; k < 64; k++) {
            float xv = xs[ln * 129 + half * 64 + k];
            const float* wr = &ws[k * HCP];
#pragma unroll
            for (int jj = 0; jj < 4; jj++) {
                int qb = cg * 4 + jj;
                if (qb < 13) {
                    float4 w4 = *(const float4*)(wr + qb * 4);
                    acc[jj].x += xv * w4.x; acc[jj].y += xv * w4.y;
                    acc[jj].z += xv * w4.z; acc[jj].w += xv * w4.w;
                }
            }
        }
    }

    int n = n0 + ln;
    float4* op = (float4*)(g_xw + n * HCP);
#pragma unroll
    for (int jj = 0; jj < 4; jj++) {
        int qb = cg * 4 + jj;
        if (qb < 13) op[qb] = acc[jj];
    }
}

// ---------------- K1b: attention dot products -------------------------------
__global__ __launch_bounds__(128) void k_att(const float* __restrict__ att_src,
                                             const float* __restrict__ att_dst) {
    __shared__ float s_as[HC], s_ad[HC];
    if (threadIdx.x < HC) { s_as[threadIdx.x] = att_src[threadIdx.x];
                            s_ad[threadIdx.x] = att_dst[threadIdx.x]; }
    __syncthreads();
    int n = blockIdx.x * blockDim.x + threadIdx.x;
    if (n >= N_NODES) return;
    const float* r = g_xw + n * HCP;
    float sa[NHEADS], sd[NHEADS];
#pragma unroll
    for (int h = 0; h < NHEADS; h++) {
        float a = 0.f, d = 0.f;
#pragma unroll
        for (int c = 0; c < 10; c++) {
            float v = r[h * 10 + c];
            a += v * s_as[h * 10 + c];
            d += v * s_ad[h * 10 + c];
        }
        sa[h] = a; sd[h] = d;
    }
    float4* ps = (float4*)(g_asrc + n * 8);
    float4* pd = (float4*)(g_adst + n * 8);
    ps[0] = make_float4(sa[0], sa[1], sa[2], sa[3]);
    ps[1] = make_float4(sa[4], 0.f, 0.f, 0.f);
    pd[0] = make_float4(sd[0], sd[1], sd[2], sd[3]);
    pd[1] = make_float4(sd[4], 0.f, 0.f, 0.f);
}

// ---------------- K2: degree count ------------------------------------------
__global__ void k_count(const int* __restrict__ ei) {
    int e = blockIdx.x * blockDim.x + threadIdx.x;
    if (e >= E_EDGES) return;
    atomicAdd(&g_deg[__ldg(ei + E_EDGES + e)], 1);
}

// ---------------- K3: two-level scan ----------------------------------------
__global__ __launch_bounds__(NCHUNK) void k_scan1() {
    __shared__ int s[NCHUNK];
    int tid = threadIdx.x;
    int i = blockIdx.x * NCHUNK + tid;
    int v = (i < N_NODES) ? g_deg[i] : 0;
    s[tid] = v;
    __syncthreads();
    for (int off = 1; off < NCHUNK; off <<= 1) {
        int t = (tid >= off) ? s[tid - off] : 0;
        __syncthreads();
        s[tid] += t;
        __syncthreads();
    }
    if (i < N_NODES) g_offl[i] = s[tid] - v;      // exclusive
    if (tid == NCHUNK - 1) g_bsum[blockIdx.x] = s[tid];
}

__global__ __launch_bounds__(128) void k_scan2() {
    __shared__ int s[128];
    int tid = threadIdx.x;
    int v = (tid < NBLK_SCAN) ? g_bsum[tid] : 0;
    s[tid] = v;
    __syncthreads();
    for (int off = 1; off < 128; off <<= 1) {
        int t = (tid >= off) ? s[tid - off] : 0;
        __syncthreads();
        s[tid] += t;
        __syncthreads();
    }
    g_bpre[tid] = s[tid] - v;                     // exclusive
}

// ---------------- K4: fill CSR ----------------------------------------------
__global__ void k_fill(const int* __restrict__ ei) {
    int e = blockIdx.x * blockDim.x + threadIdx.x;
    if (e >= E_TOT) return;
    int s, d;
    if (e < E_EDGES) { s = __ldg(ei + e); d = __ldg(ei + E_EDGES + e); }
    else             { s = d = e - E_EDGES; }
    int pos = g_offl[d] + g_bpre[d >> 10] + atomicAdd(&g_fill[d], 1);
    g_csrc[pos] = s;
}

// ---------------- K5: gather SpMM + normalize + ELU + pooled -----------------
__device__ __forceinline__ float eluf(float v) { return v > 0.f ? v : expm1f(v); }

__global__ __launch_bounds__(512) void k_spmm(const float* __restrict__ bias,
                                              const int* __restrict__ batch) {
    __shared__ float4 red[32][13];
    __shared__ float  sb[HCP];
    __shared__ int    sgf, sgl;

    int tid = threadIdx.x;
    int n_local = tid >> 4;
    int lane = tid & 15;
    int n = blockIdx.x * 32 + n_local;            // N = 32*3125 exact

    if (tid < HC) sb[tid] = bias[tid];
    if (tid >= HC && tid < HCP) sb[tid] = 0.f;
    if (tid == 0)   sgf = __ldg(batch + blockIdx.x * 32);
    if (tid == 511) sgl = __ldg(batch + blockIdx.x * 32 + 31);

    int g = __ldg(batch + n);
    int start = g_offl[n] + g_bpre[n >> 10];
    int deg = g_deg[n];

    int q = lane;                                  // quad id (valid < 13)
    int c0 = 4 * q;
    int hlo = min(c0 / 10, 4);
    int hhi = min((c0 + 3) / 10, 4);
    bool jlo1 = ((c0 + 1) / 10) == hlo || c0 + 1 >= HC;
    bool jlo2 = ((c0 + 2) / 10) == hlo || c0 + 2 >= HC;
    bool jlo3 = ((c0 + 3) / 10) == hlo || c0 + 3 >= HC;

    unsigned hm = 0xFFFFu << (tid & 16);           // half-warp mask

    float adv = 0.f;
    if (lane < NHEADS) adv = __ldg(g_adst + n * 8 + lane);

    float4 acc = make_float4(0.f, 0.f, 0.f, 0.f);
    float denlo = 0.f, denhi = 0.f;

    int i = start, end = start + deg;
    int s_cur = __ldg(g_csrc + i);
    while (i < end) {
        int s = s_cur;
        ++i;
        if (i < end) s_cur = __ldg(g_csrc + i);

        float w = 0.f;
        if (lane < NHEADS) {
            float l = __ldg(g_asrc + s * 8 + lane) + adv;
            l = l > 0.f ? l : NEG_SLOPE * l;
            w = __expf(l);
        }
        float wlo = __shfl_sync(hm, w, hlo, 16);
        float whi = __shfl_sync(hm, w, hhi, 16);

        if (lane < 13) {
            float4 v = __ldg((const float4*)(g_xw + s * HCP + c0));
            acc.x += wlo * v.x;
            acc.y += (jlo1 ? wlo : whi) * v.y;
            acc.z += (jlo2 ? wlo : whi) * v.z;
            acc.w += (jlo3 ? wlo : whi) * v.w;
        }
        denlo += wlo; denhi += whi;
    }

    __syncthreads();                               // sb / sgf ready (also before red use)

    float4 o = make_float4(0.f, 0.f, 0.f, 0.f);
    if (lane < 13) {
        float ilo = 1.f / denlo, ihi = 1.f / denhi;
        o.x = eluf(acc.x * ilo + sb[c0 + 0]);
        o.y = eluf(acc.y * (jlo1 ? ilo : ihi) + sb[c0 + 1]);
        o.z = eluf(acc.z * (jlo2 ? ilo : ihi) + sb[c0 + 2]);
        o.w = eluf(acc.w * (jlo3 ? ilo : ihi) + sb[c0 + 3]);
        if (c0 + 2 >= HC) o.z = 0.f;
        if (c0 + 3 >= HC) o.w = 0.f;
        red[n_local][q] = o;
    }
    __syncthreads();

    if (sgf == sgl) {
        // uniform graph within block: smem tree-reduce over 32 nodes
#pragma unroll
        for (int sft = 16; sft > 0; sft >>= 1) {
            if (n_local < sft && lane < 13) {
                float4 a = red[n_local][lane];
                float4 b = red[n_local + sft][lane];
                a.x += b.x; a.y += b.y; a.z += b.z; a.w += b.w;
                red[n_local][lane] = a;
            }
            __syncthreads();
        }
        if (n_local == 0 && lane < 13) {
            float4 r = red[0][lane];
            red4(&g_gsum[sgf * HCP + 4 * lane], r.x, r.y, r.z, r.w);
        }
        if (tid == 0) red1(&g_cnt[sgf], 32.f);
    } else {
        if (lane < 13) red4(&g_gsum[g * HCP + c0], o.x, o.y, o.z, o.w);
        if (lane == 0) red1(&g_cnt[g], 1.f);
    }
}

// ---------------- K6: final linear + sigmoid --------------------------------
__global__ void k_final(const float* __restrict__ lin_w,
                        const float* __restrict__ lin_b,
                        float* __restrict__ out, int out_size) {
    int g = threadIdx.x;
    float cnt = g_cnt[g];
    float inv = 1.f / fmaxf(cnt, 1.f);
    float dot = 0.f;
#pragma unroll
    for (int c = 0; c < HC; c++) {
        float h = g_gsum[g * HCP + c] * inv;
        int idx = g * HC + c;
        if (idx < out_size) out[idx] = h;
        dot += h * __ldg(lin_w + c);
    }
    float y = 1.f / (1.f + __expf(-(dot + __ldg(lin_b))));
    int yidx = NGRAPH * HC + g;
    if (yidx < out_size) out[yidx] = y;
}

// ---------------- launch -----------------------------------------------------
extern "C" void kernel_launch(void* const* d_in, const int* in_sizes, int n_in,
                              void* d_out, int out_size) {
    const float* x       = (const float*)d_in[0];
    const float* W       = (const float*)d_in[1];
    const float* att_src = (const float*)d_in[2];
    const float* att_dst = (const float*)d_in[3];
    const float* bias    = (const float*)d_in[4];
    const float* lin_w   = (const float*)d_in[5];
    const float* lin_b   = (const float*)d_in[6];
    const int*   ei      = (const int*)d_in[7];
    const int*   batch   = (const int*)d_in[8];
    float*       out     = (float*)d_out;

    k_init <<<256, 256>>>();
    k_gemm <<<(N_NODES + 31) / 32, 128>>>(x, W);
    k_att  <<<(N_NODES + 127) / 128, 128>>>(att_src, att_dst);
    k_count<<<(E_EDGES + 255) / 256, 256>>>(ei);
    k_scan1<<<NBLK_SCAN, NCHUNK>>>();
    k_scan2<<<1, 128>>>();
    k_fill <<<(E_TOT + 255) / 256, 256>>>(ei);
    k_spmm <<<N_NODES / 32, 512>>>(bias, batch);
    k_final<<<1, 256>>>(lin_w, lin_b, out, out_size);
}

// round 6
// speedup vs baseline: 1.8519x; 1.1563x over previous
#include <cuda_runtime.h>
#include <cuda_fp16.h>
#include <mma.h>
using namespace nvcuda;

#define N_NODES 100000
#define E_EDGES 1600000
#define DIM     128
#define HC      50          // H*C
#define HCW     52          // fp16 row length (26 half2, 13 x 8B)
#define NHEADS  5
#define NGRAPH  256
#define NEG_SLOPE 0.2f
#define NCHUNK  1024
#define NBLK_SCAN ((N_NODES + NCHUNK - 1) / NCHUNK)   // 98

// ---------------- scratch ----------------------------------------------------
__device__ __align__(16) __half g_xwh [N_NODES * HCW];  // fp16 projected features
__device__ __align__(16) float g_asrc [N_NODES * 8];
__device__ __align__(16) float g_adst [N_NODES * 8];
__device__ __align__(16) float g_gsum [NGRAPH * HCW];
__device__ __align__(16) float g_cnt  [NGRAPH];
__device__ int   g_deg   [N_NODES];     // in-degree (edges only)
__device__ int   g_offl  [N_NODES];     // chunk-local exclusive prefix
__device__ int   g_bpre  [128];
__device__ int   g_bsum  [128];
__device__ int   g_start [N_NODES];     // CSR start
__device__ int   g_pos   [N_NODES];     // destructive fill cursor
__device__ int   g_csrc  [E_EDGES];     // CSR: src ids grouped by dst

// ---------------- reductions -------------------------------------------------
__device__ __forceinline__ void red4(float* p, float a, float b, float c, float d) {
    asm volatile("red.global.add.v4.f32 [%0], {%1,%2,%3,%4};"
                 :: "l"(p), "f"(a), "f"(b), "f"(c), "f"(d) : "memory");
}
__device__ __forceinline__ void red1(float* p, float a) {
    asm volatile("red.global.add.f32 [%0], %1;" :: "l"(p), "f"(a) : "memory");
}

// ---------------- K0: init ---------------------------------------------------
__global__ void k_init() {
    int i = blockIdx.x * blockDim.x + threadIdx.x;
    int stride = gridDim.x * blockDim.x;
    for (int j = i; j < N_NODES; j += stride) g_deg[j] = 0;
    for (int j = i; j < NGRAPH * HCW; j += stride) g_gsum[j] = 0.f;
    for (int j = i; j < NGRAPH; j += stride) g_cnt[j] = 0.f;
}

// ---------------- K1: wmma GEMM + attention dots + fp16 store ----------------
__global__ __launch_bounds__(128) void k_gemm(const float* __restrict__ x,
                                              const float* __restrict__ W,
                                              const float* __restrict__ att_src,
                                              const float* __restrict__ att_dst) {
    __shared__ __half xs[32 * 136];      // 32x128 fp16, ldm 136
    __shared__ __half ws[128 * 64];      // 128x64 fp16 (cols 50..63 zero)
    __shared__ float  cs[32 * 68];       // 32x64 fp32 result, ldm 68
    __shared__ float  s_as[HC], s_ad[HC];

    int t = threadIdx.x, warp = t >> 5;
    int n0 = blockIdx.x * 32;

    if (t < HC) { s_as[t] = att_src[t]; s_ad[t] = att_dst[t]; }

    const float4* xg = (const float4*)(x + (size_t)n0 * DIM);
    for (int i = t; i < 32 * 32; i += 128) {
        int r = i >> 5, c4 = i & 31;
        float4 v = xg[r * 32 + c4];
        __half* p = &xs[r * 136 + c4 * 4];
        p[0] = __float2half(v.x); p[1] = __float2half(v.y);
        p[2] = __float2half(v.z); p[3] = __float2half(v.w);
    }
    for (int i = t; i < 128 * 64; i += 128) {
        int r = i >> 6, c = i & 63;
        ws[i] = __float2half(c < HC ? W[r * HC + c] : 0.f);
    }
    __syncthreads();

    // warp computes C[:, warp*16 : warp*16+16]
#pragma unroll
    for (int mt = 0; mt < 2; mt++) {
        wmma::fragment<wmma::accumulator, 16, 16, 16, float> cfrag;
        wmma::fill_fragment(cfrag, 0.f);
#pragma unroll
        for (int k = 0; k < 8; k++) {
            wmma::fragment<wmma::matrix_a, 16, 16, 16, __half, wmma::row_major> a;
            wmma::fragment<wmma::matrix_b, 16, 16, 16, __half, wmma::row_major> b;
            wmma::load_matrix_sync(a, xs + mt * 16 * 136 + k * 16, 136);
            wmma::load_matrix_sync(b, ws + k * 16 * 64 + warp * 16, 64);
            wmma::mma_sync(cfrag, a, b, cfrag);
        }
        wmma::store_matrix_sync(cs + mt * 16 * 68 + warp * 16, cfrag, 68,
                                wmma::mem_row_major);
    }
    __syncthreads();

    // fp16 store of xw (52 cols, pads zero)
    for (int i = t; i < 32 * 26; i += 128) {
        int n = i / 26, c2 = i - n * 26;
        float lo = (2 * c2     < HC) ? cs[n * 68 + 2 * c2]     : 0.f;
        float hi = (2 * c2 + 1 < HC) ? cs[n * 68 + 2 * c2 + 1] : 0.f;
        *(__half2*)(g_xwh + (size_t)(n0 + n) * HCW + 2 * c2) = __floats2half2_rn(lo, hi);
    }

    // attention dots: 160 jobs (32 nodes x 5 heads)
    for (int j = t; j < 160; j += 128) {
        int n = j / 5, h = j - 5 * n;
        const float* row = &cs[n * 68 + h * 10];
        float a = 0.f, d = 0.f;
#pragma unroll
        for (int c = 0; c < 10; c++) {
            a += row[c] * s_as[h * 10 + c];
            d += row[c] * s_ad[h * 10 + c];
        }
        g_asrc[(n0 + n) * 8 + h] = a;
        g_adst[(n0 + n) * 8 + h] = d;
    }
}

// ---------------- K2: degree count ------------------------------------------
__global__ void k_count(const int* __restrict__ ei) {
    int e = blockIdx.x * blockDim.x + threadIdx.x;
    if (e >= E_EDGES) return;
    atomicAdd(&g_deg[__ldg(ei + E_EDGES + e)], 1);
}

// ---------------- K3: two-level scan ----------------------------------------
__global__ __launch_bounds__(NCHUNK) void k_scan1() {
    __shared__ int s[NCHUNK];
    int tid = threadIdx.x;
    int i = blockIdx.x * NCHUNK + tid;
    int v = (i < N_NODES) ? g_deg[i] : 0;
    s[tid] = v;
    __syncthreads();
    for (int off = 1; off < NCHUNK; off <<= 1) {
        int tv = (tid >= off) ? s[tid - off] : 0;
        __syncthreads();
        s[tid] += tv;
        __syncthreads();
    }
    if (i < N_NODES) g_offl[i] = s[tid] - v;
    if (tid == NCHUNK - 1) g_bsum[blockIdx.x] = s[tid];
}

__global__ __launch_bounds__(128) void k_scan2() {
    __shared__ int s[128];
    int tid = threadIdx.x;
    int v = (tid < NBLK_SCAN) ? g_bsum[tid] : 0;
    s[tid] = v;
    __syncthreads();
    for (int off = 1; off < 128; off <<= 1) {
        int tv = (tid >= off) ? s[tid - off] : 0;
        __syncthreads();
        s[tid] += tv;
        __syncthreads();
    }
    g_bpre[tid] = s[tid] - v;
}

__global__ __launch_bounds__(NCHUNK) void k_scan3() {
    int i = blockIdx.x * NCHUNK + threadIdx.x;
    if (i >= N_NODES) return;
    int st = g_offl[i] + g_bpre[i >> 10];
    g_start[i] = st;
    g_pos[i]   = st;
}

// ---------------- K4: fill CSR (edges only; self-loops inline in spmm) ------
__global__ void k_fill(const int* __restrict__ ei) {
    int e = blockIdx.x * blockDim.x + threadIdx.x;
    if (e >= E_EDGES) return;
    int s = __ldg(ei + e);
    int d = __ldg(ei + E_EDGES + e);
    int pos = atomicAdd(&g_pos[d], 1);
    g_csrc[pos] = s;
}

// ---------------- K5: gather SpMM + normalize + ELU + pooled -----------------
__device__ __forceinline__ float eluf(float v) { return v > 0.f ? v : expm1f(v); }

__global__ __launch_bounds__(512) void k_spmm(const float* __restrict__ bias,
                                              const int* __restrict__ batch) {
    __shared__ float4 red[32][13];
    __shared__ float  sb[HCW];
    __shared__ int    sgf, sgl;

    int tid = threadIdx.x;
    int n_local = tid >> 4;
    int lane = tid & 15;
    int n = blockIdx.x * 32 + n_local;             // N = 32*3125 exact

    if (tid < HC) sb[tid] = bias[tid];
    if (tid >= HC && tid < HCW) sb[tid] = 0.f;
    if (tid == 0)   sgf = __ldg(batch + blockIdx.x * 32);
    if (tid == 511) sgl = __ldg(batch + blockIdx.x * 32 + 31);

    int g = __ldg(batch + n);
    int start = g_start[n];
    int deg = g_deg[n];

    int q  = lane;                                  // quad id (valid < 13)
    int c0 = 4 * q;
    int hlo = min(c0 / 10, 4);
    int hhi = min((c0 + 3) / 10, 4);
    bool jlo1 = ((c0 + 1) / 10) == hlo || c0 + 1 >= HC;
    bool jlo2 = ((c0 + 2) / 10) == hlo || c0 + 2 >= HC;
    bool jlo3 = ((c0 + 3) / 10) == hlo || c0 + 3 >= HC;

    unsigned hm = 0xFFFFu << (tid & 16);            // half-warp mask

    float adv = 0.f;
    if (lane < NHEADS) adv = __ldg(g_adst + n * 8 + lane);

    float4 acc = make_float4(0.f, 0.f, 0.f, 0.f);
    float denlo = 0.f, denhi = 0.f;

    // iteration 0 processes the implicit self-loop (s = n), then deg edges
    int end = start + deg;
    int s_next = n;
    for (int i = start; i <= end; ++i) {
        int s = s_next;
        if (i < end) s_next = __ldg(g_csrc + i);

        float w = 0.f;
        if (lane < NHEADS) {
            float l = __ldg(g_asrc + s * 8 + lane) + adv;
            l = l > 0.f ? l : NEG_SLOPE * l;
            w = __expf(l);
        }
        float wlo = __shfl_sync(hm, w, hlo, 16);
        float whi = __shfl_sync(hm, w, hhi, 16);

        if (lane < 13) {
            uint2 u = __ldg((const uint2*)(g_xwh + (size_t)s * HCW + c0));
            float2 f0 = __half22float2(*(__half2*)&u.x);
            float2 f1 = __half22float2(*(__half2*)&u.y);
            acc.x += wlo * f0.x;
            acc.y += (jlo1 ? wlo : whi) * f0.y;
            acc.z += (jlo2 ? wlo : whi) * f1.x;
            acc.w += (jlo3 ? wlo : whi) * f1.y;
        }
        denlo += wlo; denhi += whi;
    }

    __syncthreads();

    float4 o = make_float4(0.f, 0.f, 0.f, 0.f);
    if (lane < 13) {
        float ilo = 1.f / denlo, ihi = 1.f / denhi;
        o.x = eluf(acc.x * ilo + sb[c0 + 0]);
        o.y = eluf(acc.y * (jlo1 ? ilo : ihi) + sb[c0 + 1]);
        o.z = eluf(acc.z * (jlo2 ? ilo : ihi) + sb[c0 + 2]);
        o.w = eluf(acc.w * (jlo3 ? ilo : ihi) + sb[c0 + 3]);
        if (c0 + 2 >= HC) o.z = 0.f;
        if (c0 + 3 >= HC) o.w = 0.f;
        red[n_local][q] = o;
    }
    __syncthreads();

    if (sgf == sgl) {
#pragma unroll
        for (int sft = 16; sft > 0; sft >>= 1) {
            if (n_local < sft && lane < 13) {
                float4 a = red[n_local][lane];
                float4 b = red[n_local + sft][lane];
                a.x += b.x; a.y += b.y; a.z += b.z; a.w += b.w;
                red[n_local][lane] = a;
            }
            __syncthreads();
        }
        if (n_local == 0 && lane < 13) {
            float4 r = red[0][lane];
            red4(&g_gsum[sgf * HCW + 4 * lane], r.x, r.y, r.z, r.w);
        }
        if (tid == 0) red1(&g_cnt[sgf], 32.f);
    } else {
        if (lane < 13) red4(&g_gsum[g * HCW + c0], o.x, o.y, o.z, o.w);
        if (lane == 0) red1(&g_cnt[g], 1.f);
    }
}

// ---------------- K6: final linear + sigmoid --------------------------------
__global__ void k_final(const float* __restrict__ lin_w,
                        const float* __restrict__ lin_b,
                        float* __restrict__ out, int out_size) {
    int g = threadIdx.x;
    float cnt = g_cnt[g];
    float inv = 1.f / fmaxf(cnt, 1.f);
    float dot = 0.f;
#pragma unroll
    for (int c = 0; c < HC; c++) {
        float h = g_gsum[g * HCW + c] * inv;
        int idx = g * HC + c;
        if (idx < out_size) out[idx] = h;
        dot += h * __ldg(lin_w + c);
    }
    float y = 1.f / (1.f + __expf(-(dot + __ldg(lin_b))));
    int yidx = NGRAPH * HC + g;
    if (yidx < out_size) out[yidx] = y;
}

// ---------------- launch -----------------------------------------------------
extern "C" void kernel_launch(void* const* d_in, const int* in_sizes, int n_in,
                              void* d_out, int out_size) {
    const float* x       = (const float*)d_in[0];
    const float* W       = (const float*)d_in[1];
    const float* att_src = (const float*)d_in[2];
    const float* att_dst = (const float*)d_in[3];
    const float* bias    = (const float*)d_in[4];
    const float* lin_w   = (const float*)d_in[5];
    const float* lin_b   = (const float*)d_in[6];
    const int*   ei      = (const int*)d_in[7];
    const int*   batch   = (const int*)d_in[8];
    float*       out     = (float*)d_out;

    k_init <<<256, 256>>>();
    k_count<<<(E_EDGES + 255) / 256, 256>>>(ei);
    k_gemm <<<N_NODES / 32, 128>>>(x, W, att_src, att_dst);
    k_scan1<<<NBLK_SCAN, NCHUNK>>>();
    k_scan2<<<1, 128>>>();
    k_scan3<<<NBLK_SCAN, NCHUNK>>>();
    k_fill <<<(E_EDGES + 255) / 256, 256>>>(ei);
    k_spmm <<<N_NODES / 32, 512>>>(bias, batch);
    k_final<<<1, 256>>>(lin_w, lin_b, out, out_size);
}